// round 1
// baseline (speedup 1.0000x reference)
#include <cuda_runtime.h>

// Scratch for Q, V, K projections: (B*C2, H, W) fp32 each = 64 MB each.
#define HW_ (128*128)
#define NTOT (16*64)

__device__ float g_Q[NTOT * HW_];
__device__ float g_V[NTOT * HW_];
__device__ float g_K[NTOT * HW_];

// ---------------------------------------------------------------------------
// Kernel 1: fused 1x1-conv projections.
// Per block: one batch b, one tile of 128 pixels. Computes all 64 output
// channels for Q (from e, C1=16), V and K (from x, C=64).
// Thread grid 16x16: oi handles 4 output channels, pj handles 8 pixels.
// ---------------------------------------------------------------------------
__global__ __launch_bounds__(256) void qvk_kernel(
    const float* __restrict__ x, const float* __restrict__ e,
    const float* __restrict__ W1, const float* __restrict__ b1,
    const float* __restrict__ W2, const float* __restrict__ b2,
    const float* __restrict__ W3, const float* __restrict__ b3)
{
    extern __shared__ float sm[];
    float* Xs  = sm;               // [64][128]
    float* Es  = Xs + 64*128;      // [16][128]
    float* W2s = Es + 16*128;      // [64][68]  (transposed: [c][o], pad 68)
    float* W3s = W2s + 64*68;      // [64][68]
    float* W1s = W3s + 64*68;      // [16][68]
    float* b1s = W1s + 16*68;
    float* b2s = b1s + 64;
    float* b3s = b2s + 64;

    const int tid = threadIdx.x;
    const int b   = blockIdx.y;
    const int p0  = blockIdx.x * 128;

    // Load weights transposed into smem
    for (int idx = tid; idx < 4096; idx += 256) {
        int o = idx >> 6, c = idx & 63;
        W2s[c*68 + o] = W2[idx];
        W3s[c*68 + o] = W3[idx];
    }
    for (int idx = tid; idx < 1024; idx += 256) {
        int o = idx >> 4, c = idx & 15;
        W1s[c*68 + o] = W1[idx];
    }
    if (tid < 64) { b1s[tid] = b1[tid]; b2s[tid] = b2[tid]; b3s[tid] = b3[tid]; }

    // Stage input tiles
    for (int idx = tid; idx < 64*128; idx += 256) {
        int c = idx >> 7, p = idx & 127;
        Xs[idx] = x[(b*64 + c)*HW_ + p0 + p];
    }
    for (int idx = tid; idx < 16*128; idx += 256) {
        int c = idx >> 7, p = idx & 127;
        Es[idx] = e[(b*16 + c)*HW_ + p0 + p];
    }
    __syncthreads();

    const int oi = tid >> 4;   // 0..15 -> output channels oi*4 .. oi*4+3
    const int pj = tid & 15;   // 0..15 -> pixels pj*8 .. pj*8+7

    float accQ[4][8], accV[4][8], accK[4][8];
    #pragma unroll
    for (int i = 0; i < 4; i++) {
        float bq = b1s[oi*4+i], bv = b2s[oi*4+i], bk = b3s[oi*4+i];
        #pragma unroll
        for (int j = 0; j < 8; j++) { accQ[i][j] = bq; accV[i][j] = bv; accK[i][j] = bk; }
    }

    // V, K over C=64
    #pragma unroll 4
    for (int c = 0; c < 64; c++) {
        float4 a2v = *(const float4*)&W2s[c*68 + oi*4];
        float4 a3v = *(const float4*)&W3s[c*68 + oi*4];
        float4 x0  = *(const float4*)&Xs[c*128 + pj*8];
        float4 x1  = *(const float4*)&Xs[c*128 + pj*8 + 4];
        float av2[4] = {a2v.x, a2v.y, a2v.z, a2v.w};
        float av3[4] = {a3v.x, a3v.y, a3v.z, a3v.w};
        float xv[8]  = {x0.x, x0.y, x0.z, x0.w, x1.x, x1.y, x1.z, x1.w};
        #pragma unroll
        for (int i = 0; i < 4; i++)
            #pragma unroll
            for (int j = 0; j < 8; j++) {
                accV[i][j] += av2[i] * xv[j];
                accK[i][j] += av3[i] * xv[j];
            }
    }
    // Q over C1=16
    #pragma unroll 4
    for (int c = 0; c < 16; c++) {
        float4 a1v = *(const float4*)&W1s[c*68 + oi*4];
        float4 e0  = *(const float4*)&Es[c*128 + pj*8];
        float4 e1  = *(const float4*)&Es[c*128 + pj*8 + 4];
        float av1[4] = {a1v.x, a1v.y, a1v.z, a1v.w};
        float ev[8]  = {e0.x, e0.y, e0.z, e0.w, e1.x, e1.y, e1.z, e1.w};
        #pragma unroll
        for (int i = 0; i < 4; i++)
            #pragma unroll
            for (int j = 0; j < 8; j++)
                accQ[i][j] += av1[i] * ev[j];
    }

    // Write out (coalesced float4 stores)
    #pragma unroll
    for (int i = 0; i < 4; i++) {
        int o  = oi*4 + i;
        int gb = (b*64 + o)*HW_ + p0 + pj*8;
        *(float4*)&g_Q[gb]     = make_float4(accQ[i][0], accQ[i][1], accQ[i][2], accQ[i][3]);
        *(float4*)&g_Q[gb + 4] = make_float4(accQ[i][4], accQ[i][5], accQ[i][6], accQ[i][7]);
        *(float4*)&g_V[gb]     = make_float4(accV[i][0], accV[i][1], accV[i][2], accV[i][3]);
        *(float4*)&g_V[gb + 4] = make_float4(accV[i][4], accV[i][5], accV[i][6], accV[i][7]);
        *(float4*)&g_K[gb]     = make_float4(accK[i][0], accK[i][1], accK[i][2], accK[i][3]);
        *(float4*)&g_K[gb + 4] = make_float4(accK[i][4], accK[i][5], accK[i][6], accK[i][7]);
    }
}

// ---------------------------------------------------------------------------
// Kernel 2: per-head attention. One CTA per n (1024 CTAs).
//   S = Q @ V^T (128x128x128), row softmax, ctx = P @ K, row-scaled by 1/sum.
// Thread grid 16x16, 8x8 register tile per thread.
// smem: two 128x132 fp32 buffers (A: Q^T then P; B: V^T then K).
// ---------------------------------------------------------------------------
#define LDP 132

__global__ __launch_bounds__(256) void attn_kernel(float* __restrict__ out)
{
    extern __shared__ float sm[];
    float* A  = sm;              // Qs[w][h] -> later Ps[h][g]
    float* Bm = sm + 128*LDP;    // Vs[w][g] -> later Ks[g][w]

    const int tid = threadIdx.x;
    const int n   = blockIdx.x;
    const float* Q = g_Q + n*HW_;
    const float* V = g_V + n*HW_;
    const float* K = g_K + n*HW_;

    // Stage Q, V transposed (k = w major)
    for (int idx = tid; idx < HW_; idx += 256) {
        int r = idx >> 7, w = idx & 127;
        A[w*LDP + r]  = Q[idx];
        Bm[w*LDP + r] = V[idx];
    }
    __syncthreads();

    const int ti = tid >> 4;   // rows h = ti*8 + r
    const int tj = tid & 15;   // cols g = tj*8 + c

    float acc[8][8];
    #pragma unroll
    for (int r = 0; r < 8; r++)
        #pragma unroll
        for (int c = 0; c < 8; c++) acc[r][c] = 0.0f;

    // Phase A: S = Q @ V^T
    #pragma unroll 2
    for (int k = 0; k < 128; k++) {
        float4 q0 = *(const float4*)&A[k*LDP + ti*8];
        float4 q1 = *(const float4*)&A[k*LDP + ti*8 + 4];
        float4 v0 = *(const float4*)&Bm[k*LDP + tj*8];
        float4 v1 = *(const float4*)&Bm[k*LDP + tj*8 + 4];
        float qa[8] = {q0.x, q0.y, q0.z, q0.w, q1.x, q1.y, q1.z, q1.w};
        float vb[8] = {v0.x, v0.y, v0.z, v0.w, v1.x, v1.y, v1.z, v1.w};
        #pragma unroll
        for (int r = 0; r < 8; r++)
            #pragma unroll
            for (int c = 0; c < 8; c++)
                acc[r][c] += qa[r] * vb[c];
    }

    // Softmax over g (columns): reduce across the 16 tj lanes (lower 4 lane bits)
    float mrow[8], inv[8];
    #pragma unroll
    for (int r = 0; r < 8; r++) {
        float m = acc[r][0];
        #pragma unroll
        for (int c = 1; c < 8; c++) m = fmaxf(m, acc[r][c]);
        #pragma unroll
        for (int off = 1; off < 16; off <<= 1)
            m = fmaxf(m, __shfl_xor_sync(0xFFFFFFFFu, m, off));
        mrow[r] = m;
    }
    #pragma unroll
    for (int r = 0; r < 8; r++) {
        float s = 0.0f;
        #pragma unroll
        for (int c = 0; c < 8; c++) {
            float p = __expf(acc[r][c] - mrow[r]);
            acc[r][c] = p;
            s += p;
        }
        #pragma unroll
        for (int off = 1; off < 16; off <<= 1)
            s += __shfl_xor_sync(0xFFFFFFFFu, s, off);
        inv[r] = 1.0f / s;
    }

    __syncthreads();   // everyone done reading A/Bm

    // Store P row-major into A: Ps[h][g]
    #pragma unroll
    for (int r = 0; r < 8; r++) {
        int h = ti*8 + r;
        *(float4*)&A[h*LDP + tj*8]     = make_float4(acc[r][0], acc[r][1], acc[r][2], acc[r][3]);
        *(float4*)&A[h*LDP + tj*8 + 4] = make_float4(acc[r][4], acc[r][5], acc[r][6], acc[r][7]);
    }
    // Load K row-major into Bm: Ks[g][w]
    for (int idx = tid; idx < HW_; idx += 256) {
        int g = idx >> 7, w = idx & 127;
        Bm[g*LDP + w] = K[idx];
    }
    __syncthreads();

    // Phase C: ctx = P @ K
    float oac[8][8];
    #pragma unroll
    for (int r = 0; r < 8; r++)
        #pragma unroll
        for (int c = 0; c < 8; c++) oac[r][c] = 0.0f;

    #pragma unroll 2
    for (int k = 0; k < 128; k++) {
        float a[8];
        #pragma unroll
        for (int r = 0; r < 8; r++) a[r] = A[(ti*8 + r)*LDP + k];
        float4 k0 = *(const float4*)&Bm[k*LDP + tj*8];
        float4 k1 = *(const float4*)&Bm[k*LDP + tj*8 + 4];
        float kb[8] = {k0.x, k0.y, k0.z, k0.w, k1.x, k1.y, k1.z, k1.w};
        #pragma unroll
        for (int r = 0; r < 8; r++)
            #pragma unroll
            for (int c = 0; c < 8; c++)
                oac[r][c] += a[r] * kb[c];
    }

    // Row-scale by 1/rowsum and write
    #pragma unroll
    for (int r = 0; r < 8; r++) {
        int h = ti*8 + r;
        float iv = inv[r];
        int gb = n*HW_ + h*128 + tj*8;
        *(float4*)&out[gb]     = make_float4(oac[r][0]*iv, oac[r][1]*iv, oac[r][2]*iv, oac[r][3]*iv);
        *(float4*)&out[gb + 4] = make_float4(oac[r][4]*iv, oac[r][5]*iv, oac[r][6]*iv, oac[r][7]*iv);
    }
}

// ---------------------------------------------------------------------------
extern "C" void kernel_launch(void* const* d_in, const int* in_sizes, int n_in,
                              void* d_out, int out_size)
{
    const float* x  = (const float*)d_in[0];
    const float* e  = (const float*)d_in[1];
    const float* W1 = (const float*)d_in[2];
    const float* b1 = (const float*)d_in[3];
    const float* W2 = (const float*)d_in[4];
    const float* b2 = (const float*)d_in[5];
    const float* W3 = (const float*)d_in[6];
    const float* b3 = (const float*)d_in[7];
    float* out = (float*)d_out;

    const int smem1 = (64*128 + 16*128 + 64*68*2 + 16*68 + 3*64) * (int)sizeof(float);
    cudaFuncSetAttribute(qvk_kernel, cudaFuncAttributeMaxDynamicSharedMemorySize, smem1);
    qvk_kernel<<<dim3(128, 16), 256, smem1>>>(x, e, W1, b1, W2, b2, W3, b3);

    const int smem2 = 2 * 128 * LDP * (int)sizeof(float);
    cudaFuncSetAttribute(attn_kernel, cudaFuncAttributeMaxDynamicSharedMemorySize, smem2);
    attn_kernel<<<NTOT, 256, smem2>>>(out);
}